// round 3
// baseline (speedup 1.0000x reference)
#include <cuda_runtime.h>
#include <cstdint>

// ConditionalSplineSQ2D: out[b] = sum_{g,h,c} param[b,g,h,ii]*param[b,g,h,jj]*coef[g,h,c]
// B=4096, G*G=961 cells, P=8, C=36. Pure HBM stream: 126MB read once.
//
// Design: persistent CTAs (1 per SM), 1024 threads, thread t owns cell t
// (clamped for t>=961, cf zeroed) with its 36 coefficients in registers.
// Latency hiding via a per-thread cp.async (LDGSTS) ring, depth 6: each
// thread copies its cell's 32B for b+6 into its private smem slot and later
// reads it back itself -> no register cost for pipeline depth, no barrier
// needed for the ring (per-thread commit_group/wait_group). 192KB in flight
// per SM >> BW*latency product. The single __syncthreads per b is only for
// the block reduction (double-buffered warp slots, same as R1).

#define GG          961
#define NTHR        1024
#define CC          36
#define DEPTH       6
#define STAGE_BYTES (NTHR * 32)                 // 32KB per stage
#define SMEM_DYN    (DEPTH * STAGE_BYTES)       // 192KB

extern __shared__ char ring[];

__device__ __forceinline__ void cp16(uint32_t dst_smem, const void* src) {
    asm volatile("cp.async.cg.shared.global [%0], [%1], 16;"
                 :: "r"(dst_smem), "l"(src) : "memory");
}
__device__ __forceinline__ void cp_commit() {
    asm volatile("cp.async.commit_group;" ::: "memory");
}
template <int N>
__device__ __forceinline__ void cp_wait() {
    asm volatile("cp.async.wait_group %0;" :: "n"(N) : "memory");
}

__global__ __launch_bounds__(NTHR, 1)
void sq2d_kernel(const float* __restrict__ param,
                 const float* __restrict__ coef,
                 float* __restrict__ out,
                 int nB, int stride)
{
    __shared__ float red[2][32];

    const int tid  = threadIdx.x;
    const int lane = tid & 31;
    const int warp = tid >> 5;
    const bool active = (tid < GG);
    const int cell = active ? tid : (GG - 1);   // clamp: pad threads dup cell 960

    // 36 coefficients in registers for the whole kernel.
    float cf[CC];
#pragma unroll
    for (int c = 0; c < CC; c++)
        cf[c] = active ? coef[cell * CC + c] : 0.0f;

    // Per-thread ring slot addresses (shared-space u32).
    const uint32_t slot0 = (uint32_t)__cvta_generic_to_shared(ring) + (uint32_t)tid * 32;
    // Global source base for this thread's cell.
    const char* src_base = (const char*)param + (size_t)cell * 32;
    const size_t bstep = (size_t)GG * 32;       // 30752 bytes per b

    // Prefill DEPTH stages.
    {
        int bp = blockIdx.x;
#pragma unroll
        for (int s = 0; s < DEPTH; s++) {
            if (bp < nB) {
                const char* src = src_base + (size_t)bp * bstep;
                uint32_t dst = slot0 + s * STAGE_BYTES;
                cp16(dst, src);
                cp16(dst + 16, src + 16);
            }
            cp_commit();
            bp += stride;
        }
    }

    int s = 0, buf = 0;
    for (int b = blockIdx.x; b < nB; b += stride) {
        cp_wait<DEPTH - 1>();   // oldest stage landed (own copies -> own visibility)

        const float4* p4 = reinterpret_cast<const float4*>(
            ring + (size_t)s * STAGE_BYTES + (size_t)tid * 32);
        float4 a0 = p4[0];
        float4 a1 = p4[1];
        float pv[8] = { a0.x, a0.y, a0.z, a0.w, a1.x, a1.y, a1.z, a1.w };

        // acc = sum_{i<=j} cf[c(i,j)] * p_i * p_j : 44 FMA.
        float acc = 0.0f;
        int c = 0;
#pragma unroll
        for (int i = 0; i < 8; i++) {
            float q = 0.0f;
#pragma unroll
            for (int j = i; j < 8; j++)
                q = fmaf(cf[c++], pv[j], q);
            acc = fmaf(pv[i], q, acc);
        }

        // Refill slot s for b + DEPTH*stride (this thread just finished reading it).
        {
            int bn = b + DEPTH * stride;
            if (bn < nB) {
                const char* src = src_base + (size_t)bn * bstep;
                uint32_t dst = slot0 + s * STAGE_BYTES;
                cp16(dst, src);
                cp16(dst + 16, src + 16);
            }
            cp_commit();    // always commit so group accounting stays uniform
        }

        // Block reduction (the only barrier per iteration).
#pragma unroll
        for (int o = 16; o > 0; o >>= 1)
            acc += __shfl_xor_sync(0xffffffffu, acc, o);
        if (lane == 0) red[buf][warp] = acc;

        __syncthreads();

        if (warp == 0) {
            float v = red[buf][lane];
#pragma unroll
            for (int o = 16; o > 0; o >>= 1)
                v += __shfl_xor_sync(0xffffffffu, v, o);
            if (lane == 0) out[b] = v;
        }

        buf ^= 1;
        s = (s + 1 == DEPTH) ? 0 : s + 1;
    }
}

extern "C" void kernel_launch(void* const* d_in, const int* in_sizes, int n_in,
                              void* d_out, int out_size)
{
    const float* param = (const float*)d_in[0];   // [B, 31, 31, 8] f32
    const float* coef  = (const float*)d_in[1];   // [31, 31, 36]   f32
    float* out = (float*)d_out;                    // [B] f32

    const int nB = in_sizes[0] / (GG * 8);

    static int configured = -1;
    if (configured < 0) {
        cudaFuncSetAttribute(sq2d_kernel,
                             cudaFuncAttributeMaxDynamicSharedMemorySize, SMEM_DYN);
        configured = 1;
    }

    int dev = 0, sms = 0;
    cudaGetDevice(&dev);
    cudaDeviceGetAttribute(&sms, cudaDevAttrMultiProcessorCount, dev);
    if (sms <= 0) sms = 148;
    if (sms > nB) sms = nB;

    sq2d_kernel<<<sms, NTHR, SMEM_DYN>>>(param, coef, out, nB, sms);
}

// round 4
// speedup vs baseline: 2.0945x; 2.0945x over previous
#include <cuda_runtime.h>

// ConditionalSplineSQ2D: out[b] = sum_{g,h,c} param[b,g,h,ii]*param[b,g,h,jj]*coef[g,h,c]
// B=4096, G*G=961 cells, P=8, C=36. Pure HBM stream: 126MB read once.
//
// R1 structure (thread t owns cell t, 36 coefs in registers, 2xLDG.128 per b,
// register double-buffer prefetch) but with the per-b __syncthreads removed:
// warps write their per-b partial to smem and only synchronize once per batch
// of 8 b's; warp k then does the final cross-warp reduce for b_k. Decoupled
// warps keep ~32KB/SM of independent loads in flight (vs 8KB lockstep in R1),
// which is what HBM needs at this BW-latency product.

#define GG    961
#define CC    36
#define NTHR  1024
#define BATCH 8

__global__ __launch_bounds__(NTHR, 1)
void sq2d_kernel(const float* __restrict__ param,
                 const float* __restrict__ coef,
                 float* __restrict__ out,
                 int nB, int stride)
{
    __shared__ float red[2][BATCH][32];

    const int tid  = threadIdx.x;
    const int lane = tid & 31;
    const int warp = tid >> 5;
    const bool active = (tid < GG);
    const int cell = active ? tid : (GG - 1);   // clamp: pad threads dup cell 960

    // 36 coefficients in registers for the whole kernel (cf=0 for pad threads,
    // so their garbage-free but duplicated loads contribute nothing).
    float cf[CC];
#pragma unroll
    for (int c = 0; c < CC; c++)
        cf[c] = active ? coef[cell * CC + c] : 0.0f;

    // param as float4: per-b stride = 961*2 float4.
    const float4* pbase = reinterpret_cast<const float4*>(param) + (size_t)cell * 2;
    const size_t bstep4 = (size_t)GG * 2;

    int b = blockIdx.x;
    float4 n0, n1;
    if (b < nB) {
        const float4* p = pbase + (size_t)b * bstep4;
        n0 = p[0];
        n1 = p[1];
    }

    int buf = 0;
    while (b < nB) {
        const int bstart = b;
        int cnt = 0;

#pragma unroll 1
        for (int k = 0; k < BATCH && b < nB; k++) {
            float4 a0 = n0, a1 = n1;

            // Prefetch next b immediately (lands while we compute + batch-mates run).
            const int bn = b + stride;
            if (bn < nB) {
                const float4* p = pbase + (size_t)bn * bstep4;
                n0 = p[0];
                n1 = p[1];
            }

            float pv[8] = { a0.x, a0.y, a0.z, a0.w, a1.x, a1.y, a1.z, a1.w };

            // acc = sum_{i<=j} cf[c(i,j)] * p_i * p_j : 44 FMA.
            float acc = 0.0f;
            int c = 0;
#pragma unroll
            for (int i = 0; i < 8; i++) {
                float q = 0.0f;
#pragma unroll
                for (int j = i; j < 8; j++)
                    q = fmaf(cf[c++], pv[j], q);
                acc = fmaf(pv[i], q, acc);
            }

            // Warp reduce; NO block barrier here.
#pragma unroll
            for (int o = 16; o > 0; o >>= 1)
                acc += __shfl_xor_sync(0xffffffffu, acc, o);
            if (lane == 0) red[buf][k][warp] = acc;

            b = bn;
            cnt++;
        }

        __syncthreads();   // one barrier per BATCH b's

        // Warp k finishes b_k. Next batch writes red[buf^1]; the batch after
        // that reuses red[buf] but only past the next __syncthreads, which
        // orders it after these reads.
        if (warp < cnt) {
            float v = red[buf][warp][lane];
#pragma unroll
            for (int o = 16; o > 0; o >>= 1)
                v += __shfl_xor_sync(0xffffffffu, v, o);
            if (lane == 0) out[bstart + warp * stride] = v;
        }

        buf ^= 1;
    }
}

extern "C" void kernel_launch(void* const* d_in, const int* in_sizes, int n_in,
                              void* d_out, int out_size)
{
    const float* param = (const float*)d_in[0];   // [B, 31, 31, 8] f32
    const float* coef  = (const float*)d_in[1];   // [31, 31, 36]   f32
    float* out = (float*)d_out;                    // [B] f32

    const int nB = in_sizes[0] / (GG * 8);

    int dev = 0, sms = 0;
    cudaGetDevice(&dev);
    cudaDeviceGetAttribute(&sms, cudaDevAttrMultiProcessorCount, dev);
    if (sms <= 0) sms = 148;
    if (sms > nB) sms = nB;

    sq2d_kernel<<<sms, NTHR>>>(param, coef, out, nB, sms);
}